// round 2
// baseline (speedup 1.0000x reference)
#include <cuda_runtime.h>

// out[i] = x[i] - max(ceil(x[i]), 1.0f)
// Streaming elementwise: vec4, 4x unrolled with front-batched loads (MLP=4),
// streaming cache hints (zero-reuse working set).

__device__ __forceinline__ float f(float v) {
    return v - fmaxf(ceilf(v), 1.0f);
}

__device__ __forceinline__ float4 f4(float4 v) {
    float4 r;
    r.x = f(v.x); r.y = f(v.y); r.z = f(v.z); r.w = f(v.w);
    return r;
}

__global__ void __launch_bounds__(256)
recur_kernel_vec4_u4(const float4* __restrict__ x, float4* __restrict__ out, long n4) {
    long stride = (long)gridDim.x * blockDim.x;
    long i = (long)blockIdx.x * blockDim.x + threadIdx.x;

    // Main unrolled-by-4 region: front-batch 4 independent 128-bit loads.
    long limit = n4 - 3 * stride;
    for (; i < limit; i += 4 * stride) {
        float4 v0 = __ldcs(&x[i]);
        float4 v1 = __ldcs(&x[i + stride]);
        float4 v2 = __ldcs(&x[i + 2 * stride]);
        float4 v3 = __ldcs(&x[i + 3 * stride]);
        __stcs(&out[i],              f4(v0));
        __stcs(&out[i + stride],     f4(v1));
        __stcs(&out[i + 2 * stride], f4(v2));
        __stcs(&out[i + 3 * stride], f4(v3));
    }
    // Remainder
    for (; i < n4; i += stride) {
        __stcs(&out[i], f4(__ldcs(&x[i])));
    }
}

__global__ void recur_kernel_tail(const float* __restrict__ x, float* __restrict__ out,
                                  long start, long n) {
    long i = start + (long)blockIdx.x * blockDim.x + threadIdx.x;
    if (i < n) out[i] = f(x[i]);
}

extern "C" void kernel_launch(void* const* d_in, const int* in_sizes, int n_in,
                              void* d_out, int out_size) {
    const float* x = (const float*)d_in[0];
    float* out = (float*)d_out;
    long n = (long)in_sizes[0];

    long n4 = n / 4;
    if (n4 > 0) {
        int threads = 256;
        long want = (n4 + threads - 1) / threads;
        long maxBlocks = 148L * 8;  // 1184 CTAs, ~8/SM
        int blocks = (int)((want < maxBlocks) ? want : maxBlocks);
        recur_kernel_vec4_u4<<<blocks, threads>>>((const float4*)x, (float4*)out, n4);
    }
    long rem_start = n4 * 4;
    long rem = n - rem_start;
    if (rem > 0) {
        int threads = 256;
        int blocks = (int)((rem + threads - 1) / threads);
        recur_kernel_tail<<<blocks, threads>>>(x, out, rem_start, n);
    }
}

// round 5
// speedup vs baseline: 1.1175x; 1.1175x over previous
#include <cuda_runtime.h>

// out[i] = x[i] - max(ceil(x[i]), 1.0f)
// Flat streaming kernel: one float4 per thread, 32-bit indexing, streaming hints.
// n = 32*4096*1024 = 2^27, so n4 = 2^25 and the tail path never runs in practice.

__device__ __forceinline__ float f(float v) {
    return v - fmaxf(ceilf(v), 1.0f);
}

__global__ void __launch_bounds__(256)
recur_kernel_flat(const float4* __restrict__ x, float4* __restrict__ out, unsigned n4) {
    unsigned i = blockIdx.x * 256u + threadIdx.x;
    if (i < n4) {
        float4 v = __ldcs(&x[i]);
        float4 r;
        r.x = f(v.x); r.y = f(v.y); r.z = f(v.z); r.w = f(v.w);
        __stcs(&out[i], r);
    }
}

__global__ void recur_kernel_tail(const float* __restrict__ x, float* __restrict__ out,
                                  long start, long n) {
    long i = start + (long)blockIdx.x * blockDim.x + threadIdx.x;
    if (i < n) out[i] = f(x[i]);
}

extern "C" void kernel_launch(void* const* d_in, const int* in_sizes, int n_in,
                              void* d_out, int out_size) {
    const float* x = (const float*)d_in[0];
    float* out = (float*)d_out;
    long n = (long)in_sizes[0];

    long n4 = n / 4;
    if (n4 > 0) {
        unsigned un4 = (unsigned)n4;
        unsigned blocks = (un4 + 255u) / 256u;
        recur_kernel_flat<<<blocks, 256>>>((const float4*)x, (float4*)out, un4);
    }
    long rem_start = n4 * 4;
    long rem = n - rem_start;
    if (rem > 0) {
        int threads = 256;
        int blocks = (int)((rem + threads - 1) / threads);
        recur_kernel_tail<<<blocks, threads>>>(x, out, rem_start, n);
    }
}

// round 6
// speedup vs baseline: 1.1403x; 1.0205x over previous
#include <cuda_runtime.h>

// out[i] = x[i] - max(ceil(x[i]), 1.0f)
// Flat streaming kernel: TWO float4 per thread (front-batched, independent),
// 32-bit indexing, streaming cache hints. n = 2^27 -> n4 = 2^25 (even), so the
// two halves split exactly; guards cover any other shape.

__device__ __forceinline__ float f(float v) {
    return v - fmaxf(ceilf(v), 1.0f);
}

__device__ __forceinline__ float4 f4(float4 v) {
    float4 r;
    r.x = f(v.x); r.y = f(v.y); r.z = f(v.z); r.w = f(v.w);
    return r;
}

__global__ void __launch_bounds__(256)
recur_kernel_flat2(const float4* __restrict__ x, float4* __restrict__ out,
                   unsigned half, unsigned n4) {
    unsigned i = blockIdx.x * 256u + threadIdx.x;
    if (i < half) {
        // Two independent 128-bit loads in flight before any store.
        float4 v0 = __ldcs(&x[i]);
        unsigned j = i + half;
        if (j < n4) {
            float4 v1 = __ldcs(&x[j]);
            __stcs(&out[i], f4(v0));
            __stcs(&out[j], f4(v1));
        } else {
            __stcs(&out[i], f4(v0));
        }
    }
}

__global__ void recur_kernel_tail(const float* __restrict__ x, float* __restrict__ out,
                                  long start, long n) {
    long i = start + (long)blockIdx.x * blockDim.x + threadIdx.x;
    if (i < n) out[i] = f(x[i]);
}

extern "C" void kernel_launch(void* const* d_in, const int* in_sizes, int n_in,
                              void* d_out, int out_size) {
    const float* x = (const float*)d_in[0];
    float* out = (float*)d_out;
    long n = (long)in_sizes[0];

    long n4 = n / 4;
    if (n4 > 0) {
        unsigned un4 = (unsigned)n4;
        unsigned half = (un4 + 1u) / 2u;   // first slot covers [0, half), second [half, n4)
        unsigned blocks = (half + 255u) / 256u;
        recur_kernel_flat2<<<blocks, 256>>>((const float4*)x, (float4*)out, half, un4);
    }
    long rem_start = n4 * 4;
    long rem = n - rem_start;
    if (rem > 0) {
        int threads = 256;
        int blocks = (int)((rem + threads - 1) / threads);
        recur_kernel_tail<<<blocks, threads>>>(x, out, rem_start, n);
    }
}